// round 12
// baseline (speedup 1.0000x reference)
#include <cuda_runtime.h>
#include <cstdint>

#define NQ   14
#define TPB  512
typedef unsigned long long ull;

__device__ __forceinline__ int pf_(int x) {
    x ^= x >> 1; x ^= x >> 2; x ^= x >> 4; x ^= x >> 8;
    return x;
}

__device__ __forceinline__ ull f2mul(ull a, ull b) {
    ull r; asm("mul.rn.f32x2 %0,%1,%2;" : "=l"(r) : "l"(a), "l"(b)); return r;
}
__device__ __forceinline__ ull f2fma(ull a, ull b, ull c) {
    ull r; asm("fma.rn.f32x2 %0,%1,%2,%3;" : "=l"(r) : "l"(a), "l"(b), "l"(c)); return r;
}
__device__ __forceinline__ ull pk2(float x, float y) {
    ull r; asm("mov.b64 %0,{%1,%2};" : "=l"(r) : "f"(x), "f"(y)); return r;
}
__device__ __forceinline__ float2 upk(ull a) {
    float2 r; asm("mov.b64 {%0,%1},%2;" : "=f"(r.x), "=f"(r.y) : "l"(a)); return r;
}
__device__ __forceinline__ ull swp(ull a) { float2 t = upk(a); return pk2(t.y, t.x); }
__device__ __forceinline__ ull bc(float x) { return pk2(x, x); }

__device__ __forceinline__ float2 cmul_s(float2 a, float2 b) {
    return make_float2(a.x * b.x - a.y * b.y, a.x * b.y + a.y * b.x);
}

#define SPAD 8704   // 8192 pairs + 512 pad (1 per 16), pad A(p)=p+(p>>4)

__global__ void __launch_bounds__(TPB, 1)
qsim_kernel(const float* __restrict__ sb, const float* __restrict__ vp,
            const float* __restrict__ hw, const float* __restrict__ hb,
            float* __restrict__ out)
{
    extern __shared__ unsigned char smraw[];
    ulonglong2* sRI = (ulonglong2*)smraw;        // 8704 x 16B = {re, im} per pair
    ull*    PloRe = (ull*)(sRI + SPAD);          // 2*64 (layers 0,1), [L][r*4+c]
    ull*    PloIm = PloRe + 128;                 // 2*64
    ull*    Wlo2  = PloIm + 128;                 // 64 (scalar view Wlo[128])
    float*  tanw  = (float*)(Wlo2 + 64);         // 48 (42 used)
    float*  cosw  = tanw + 48;                   // 48 (42 used)
    float2* phw   = (float2*)(cosw + 48);        // 48 (28 used)
    float*  PhiRe = (float*)(phw + 48);          // 256
    float*  PhiIm = PhiRe + 256;                 // 256
    float*  cx    = PhiIm + 256;                 // 16
    float*  sx    = cx + 16;                     // 16
    float*  Whi   = sx + 16;                     // 128
    float*  red   = Whi + 128;                   // 16
    float*  WloF  = (float*)Wlo2;

    const int t = threadIdx.x;
    const int b = blockIdx.x;

    // ---- stage 1: parameter staging ----
    if (t < NQ) {
        float s, c; sincosf(0.5f * sb[b * NQ + t], &s, &c);
        cx[t] = c; sx[t] = s;
    }
    if (t >= 64 && t < 64 + 3 * NQ) {
        int lw = t - 64;
        float sa, ca;
        sincosf(0.5f * vp[lw * 3 + 0], &sa, &ca);
        tanw[lw] = __fdividef(sa, ca);
        cosw[lw] = ca;
        if (lw < 2 * NQ) {
            float sp, cp;
            sincosf(vp[lw * 3 + 1], &sp, &cp);
            phw[lw] = make_float2(cp, sp);
        }
    }
    __syncthreads();

    // ---- stage 2: LUT builds (phases for L=0,1; cos^2-scaled weights) ----
    if (t < 256) {
        int L = t >> 7, v = t & 127;
        float2 pl = make_float2(1.f, 0.f), ph = make_float2(1.f, 0.f);
        #pragma unroll
        for (int k = 0; k < 7; k++) {
            if ((v >> k) & 1) {
                pl = cmul_s(pl, phw[L * NQ + (13 - k)]);
                ph = cmul_s(ph, phw[L * NQ + (6 - k)]);
            }
        }
        PhiRe[t] = ph.x; PhiIm[t] = ph.y;
        int c = v >> 5, r = (v >> 1) & 15, b0 = v & 1;
        ((float*)PloRe)[2 * (L * 64 + r * 4 + c) + b0] = pl.x;
        ((float*)PloIm)[2 * (L * 64 + r * 4 + c) + b0] = pl.y;
    } else {
        float prod = 1.f;
        #pragma unroll
        for (int k = 0; k < 3 * NQ; k++) prod *= cosw[k];
        prod *= prod;
        if (t < 384) {
            int v = t - 256; float acc = 0.f;
            #pragma unroll
            for (int k = 0; k < 7; k++)
                acc += hw[13 - k] * (1.f - 2.f * (float)((v >> k) & 1));
            WloF[v] = acc * prod;
        } else {
            int v = t - 384; float acc = 0.f;
            #pragma unroll
            for (int k = 0; k < 7; k++)
                acc += hw[6 - k] * (1.f - 2.f * (float)((v >> k) & 1));
            Whi[v] = acc * prod;
        }
    }

    ull vre[16], vim[16];

    // tangent-form RY on tile bit lb
    auto applyW = [&](float tg, int lb) {
        ull tp = bc(tg), tn = bc(-tg);
        #pragma unroll
        for (int m = 0; m < 8; m++) {
            int l0 = ((m >> lb) << (lb + 1)) | (m & ((1 << lb) - 1));
            int l1 = l0 | (1 << lb);
            ull r0 = f2fma(tn, vre[l1], vre[l0]);
            ull r1 = f2fma(tp, vre[l0], vre[l1]);
            vre[l0] = r0; vre[l1] = r1;
            ull i0 = f2fma(tn, vim[l1], vim[l0]);
            ull i1 = f2fma(tp, vim[l0], vim[l1]);
            vim[l0] = i0; vim[l1] = i1;
        }
    };

    // affine pass bases (padding A(p) = p + (p>>4))
    const int b1 = t + (t >> 4);                               // + 544*r
    const int b2 = (t >> 5) * 544 + (t & 31) + ((t >> 4) & 1); // + 34*r
    const int b3 = 34 * (t >> 1) + (t & 1);                    // + 2r + (r>>3)
    const int b4 = 17 * t;                                     // + r

    // ---- init: closed-form RX + layer-0 wires 0..3 (tan form) ----
    {
        float mt = 1.f;
        #pragma unroll
        for (int k = 0; k < 9; k++)
            mt *= ((t >> k) & 1) ? sx[12 - k] : cx[12 - k];
        int pt = __popc(t);
        #pragma unroll
        for (int r = 0; r < 16; r++) {
            float mr = mt;
            #pragma unroll
            for (int m = 0; m < 4; m++)
                mr *= ((r >> m) & 1) ? sx[3 - m] : cx[3 - m];
            int pr = pt + __popc(r);
            float m0 = mr * cx[13], m1 = mr * sx[13];
            int k0 = pr & 3, k1 = (pr + 1) & 3;
            float re0 = (k0 == 0) ? m0 : ((k0 == 2) ? -m0 : 0.f);
            float im0 = (k0 == 1) ? -m0 : ((k0 == 3) ? m0 : 0.f);
            float re1 = (k1 == 0) ? m1 : ((k1 == 2) ? -m1 : 0.f);
            float im1 = (k1 == 1) ? -m1 : ((k1 == 3) ? m1 : 0.f);
            vre[r] = pk2(re0, re1); vim[r] = pk2(im0, im1);
        }
        __syncthreads();   // stage-2 LUT writes complete
        #pragma unroll
        for (int lb = 0; lb < 4; lb++) applyW(tanw[3 - lb], lb);
        #pragma unroll
        for (int r = 0; r < 16; r++)
            sRI[b1 + 544 * r] = make_ulonglong2(vre[r], vim[r]);
    }
    __syncthreads();

    #pragma unroll 1
    for (int L = 0; L < 3; L++) {
        // ---- P2: wires 4..7 ----
        {
            #pragma unroll
            for (int r = 0; r < 16; r++) {
                ulonglong2 x = sRI[b2 + 34 * r];
                vre[r] = x.x; vim[r] = x.y;
            }
            #pragma unroll
            for (int lb = 0; lb < 4; lb++) applyW(tanw[L * NQ + (7 - lb)], lb);
            #pragma unroll
            for (int r = 0; r < 16; r++)
                sRI[b2 + 34 * r] = make_ulonglong2(vre[r], vim[r]);
        }
        __syncwarp(0xffffffffu);   // P2->P3 warp-local (pair bits 12..9 = warp id)

        // ---- P3: wires 8..11 ----
        {
            #pragma unroll
            for (int r = 0; r < 16; r++) {
                ulonglong2 x = sRI[b3 + 2 * r + (r >> 3)];
                vre[r] = x.x; vim[r] = x.y;
            }
            #pragma unroll
            for (int lb = 0; lb < 4; lb++) applyW(tanw[L * NQ + (11 - lb)], lb);
            #pragma unroll
            for (int r = 0; r < 16; r++)
                sRI[b3 + 2 * r + (r >> 3)] = make_ulonglong2(vre[r], vim[r]);
        }
        __syncwarp(0xffffffffu);   // P3->P4 warp-local

        // ---- P4: wires 12,13; phase for L<2; fused measurement at L=2 ----
        {
            #pragma unroll
            for (int r = 0; r < 16; r++) {
                ulonglong2 x = sRI[b4 + r];
                vre[r] = x.x; vim[r] = x.y;
            }
            applyW(tanw[L * NQ + 12], 0);
            {
                // wire 13 (lane): v' = v + tm * swp(v), tm = (-t13, t13)
                ull tm = pk2(-tanw[L * NQ + 13], tanw[L * NQ + 13]);
                #pragma unroll
                for (int r = 0; r < 16; r++) {
                    vre[r] = f2fma(tm, swp(vre[r]), vre[r]);
                    vim[r] = f2fma(tm, swp(vim[r]), vim[r]);
                }
            }
            if (L < 2) {
                float fr = PhiRe[L * 128 + (t >> 2)];
                float fi = PhiIm[L * 128 + (t >> 2)];
                ull fr2 = bc(fr), fi2 = bc(fi), nfi2 = bc(-fi), n1 = bc(-1.f);
                const int c = t & 3;
                #pragma unroll
                for (int r = 0; r < 16; r++) {
                    ull pr2 = PloRe[L * 64 + r * 4 + c];
                    ull pi2 = PloIm[L * 64 + r * 4 + c];
                    ull cr  = f2fma(fr2, pr2, f2mul(nfi2, pi2));
                    ull ci  = f2fma(fr2, pi2, f2mul(fi2, pr2));
                    ull nci = f2mul(n1, ci);
                    ull re = vre[r], im = vim[r];
                    vre[r] = f2fma(cr, re, f2mul(nci, im));
                    vim[r] = f2fma(cr, im, f2mul(ci,  re));
                }
                #pragma unroll
                for (int r = 0; r < 16; r++)
                    sRI[b4 + r] = make_ulonglong2(vre[r], vim[r]);
            } else {
                // ---- measurement from registers (chain folded, scaled W) ----
                const int ftt = pf_(t << 5);
                const float whi = Whi[ftt >> 7];
                ull acc2 = bc(0.f);
                #pragma unroll
                for (int k = 0; k < 16; k++) {
                    ull pr2 = f2fma(vim[k], vim[k], f2mul(vre[k], vre[k]));
                    int f0 = (ftt ^ pf_(k << 1)) & 127;
                    float w0 = WloF[f0]     + whi;
                    float w1 = WloF[f0 ^ 1] + whi;
                    acc2 = f2fma(pr2, pk2(w0, w1), acc2);
                }
                float2 ac = upk(acc2);
                float acc = ac.x + ac.y;
                #pragma unroll
                for (int o = 16; o > 0; o >>= 1)
                    acc += __shfl_xor_sync(0xffffffffu, acc, o);
                if ((t & 31) == 0) red[t >> 5] = acc;
                __syncthreads();
                if (t == 0) {
                    float s = 0.f;
                    #pragma unroll
                    for (int w = 0; w < TPB / 32; w++) s += red[w];
                    out[b] = s + hb[0];
                }
            }
        }

        if (L < 2) {
            __syncthreads();   // P4 writes visible block-wide before global fold
            // ---- P1' of next layer with CNOT-chain fold ----
            const int e  = t ^ (t >> 1);
            const int eh = e >> 4;
            #pragma unroll
            for (int r = 0; r < 16; r++) {
                const int C = (r << 1) ^ r;          // compile-time
                int p = e ^ (C << 8);
                int a = p + (eh ^ (C << 4));
                ulonglong2 x = sRI[a];
                vre[r] = x.x; vim[r] = x.y;
            }
            if (t & 1) {   // reader-side lane swap (output pair bit0 = t&1)
                #pragma unroll
                for (int r = 0; r < 16; r++) { vre[r] = swp(vre[r]); vim[r] = swp(vim[r]); }
            }
            #pragma unroll
            for (int lb = 0; lb < 4; lb++) applyW(tanw[(L + 1) * NQ + (3 - lb)], lb);
            __syncthreads();   // all fold reads done before rewrites
            #pragma unroll
            for (int r = 0; r < 16; r++)
                sRI[b1 + 544 * r] = make_ulonglong2(vre[r], vim[r]);
            __syncthreads();
        }
    }
}

extern "C" void kernel_launch(void* const* d_in, const int* in_sizes, int n_in,
                              void* d_out, int out_size) {
    const float* sb = (const float*)d_in[0];
    const float* vp = (const float*)d_in[1];
    const float* hw = (const float*)d_in[2];
    const float* hb = (const float*)d_in[3];
    float* out = (float*)d_out;

    const int B = in_sizes[0] / NQ;
    const size_t smem = (size_t)SPAD * 16                      // sRI interleaved
                      + (size_t)(128 * 2 + 64) * 8             // Plo*, Wlo2
                      + (48 + 48) * 4 + 48 * 8                 // tanw, cosw, phw
                      + (256 * 2 + 32 + 128 + 16) * 4;         // PhiRe/Im,cx,sx,Whi,red
    cudaFuncSetAttribute(qsim_kernel,
                         cudaFuncAttributeMaxDynamicSharedMemorySize, (int)smem);
    qsim_kernel<<<B, TPB, smem>>>(sb, vp, hw, hb, out);
}

// round 13
// speedup vs baseline: 1.4353x; 1.4353x over previous
#include <cuda_runtime.h>
#include <cstdint>

#define NQ   14
#define TPB  512
typedef unsigned long long ull;

__device__ __forceinline__ int pf_(int x) {
    x ^= x >> 1; x ^= x >> 2; x ^= x >> 4; x ^= x >> 8;
    return x;
}

__device__ __forceinline__ ull f2mul(ull a, ull b) {
    ull r; asm("mul.rn.f32x2 %0,%1,%2;" : "=l"(r) : "l"(a), "l"(b)); return r;
}
__device__ __forceinline__ ull f2fma(ull a, ull b, ull c) {
    ull r; asm("fma.rn.f32x2 %0,%1,%2,%3;" : "=l"(r) : "l"(a), "l"(b), "l"(c)); return r;
}
__device__ __forceinline__ ull pk2(float x, float y) {
    ull r; asm("mov.b64 %0,{%1,%2};" : "=l"(r) : "f"(x), "f"(y)); return r;
}
__device__ __forceinline__ float2 upk(ull a) {
    float2 r; asm("mov.b64 {%0,%1},%2;" : "=f"(r.x), "=f"(r.y) : "l"(a)); return r;
}
__device__ __forceinline__ ull swp(ull a) { float2 t = upk(a); return pk2(t.y, t.x); }
__device__ __forceinline__ ull bc(float x) { return pk2(x, x); }

__device__ __forceinline__ float2 cmul_s(float2 a, float2 b) {
    return make_float2(a.x * b.x - a.y * b.y, a.x * b.y + a.y * b.x);
}

#define SPAD 8704   // 8192 pairs + 512 pad (1 per 16), pad A(p)=p+(p>>4)

__global__ void __launch_bounds__(TPB, 1)
qsim_kernel(const float* __restrict__ sb, const float* __restrict__ vp,
            const float* __restrict__ hw, const float* __restrict__ hb,
            float* __restrict__ out)
{
    extern __shared__ unsigned char smraw[];
    ull*    sRe   = (ull*)smraw;             // 8704
    ull*    sIm   = sRe + SPAD;              // 8704
    ull*    PloRe = sIm + SPAD;              // 64 (layer 1 only), [r*4+c]
    ull*    PloIm = PloRe + 64;              // 64
    ull*    Wlo2  = PloIm + 64;              // 64 (scalar view Wlo[128])
    float*  tanw  = (float*)(Wlo2 + 64);     // 48 (uses 14..41)
    float*  cosw  = tanw + 48;               // 48 (uses 14..41)
    float2* phw   = (float2*)(cosw + 48);    // 16 (14 used: layer-1 RZ)
    float2* uw0   = phw + 16;                // 16 (14 used: layer-0 per-wire |0>-component)
    float2* uw1   = uw0 + 16;                // 16
    float*  PhiRe = (float*)(uw1 + 16);      // 128
    float*  PhiIm = PhiRe + 128;             // 128
    float*  Whi   = PhiIm + 128;             // 128
    float*  red   = Whi + 128;               // 16
    float*  WloF  = (float*)Wlo2;

    const int t = threadIdx.x;
    const int b = blockIdx.x;

    // ---- stage 1: parameter staging ----
    if (t < NQ) {
        // u_w = RZ(theta)*RY(a)*RX(x)|0>  (layer 0 folded into product state)
        float xs, xc; sincosf(0.5f * sb[b * NQ + t], &xs, &xc);
        float sa, ca; sincosf(0.5f * vp[t * 3 + 0], &sa, &ca);
        float sp, cp; sincosf(vp[t * 3 + 1], &sp, &cp);   // RZ -> diag(1, e^{i th})
        uw0[t] = make_float2(ca * xc, sa * xs);
        float u1r = sa * xc, u1i = -ca * xs;
        uw1[t] = make_float2(cp * u1r - sp * u1i, sp * u1r + cp * u1i);
    }
    if (t >= 64 && t < 64 + 2 * NQ) {        // lw in [14, 42): layers 1,2
        int lw = t - 64 + NQ;
        float sa, ca;
        sincosf(0.5f * vp[lw * 3 + 0], &sa, &ca);
        tanw[lw] = __fdividef(sa, ca);
        cosw[lw] = ca;
        if (lw < 2 * NQ) {                   // layer-1 RZ phases
            float sp, cp;
            sincosf(vp[lw * 3 + 1], &sp, &cp);
            phw[lw - NQ] = make_float2(cp, sp);
        }
    }
    __syncthreads();

    // ---- stage 2: LUT builds (layer-1 phase; cos^2-scaled weights) ----
    if (t < 128) {
        int v = t;
        float2 pl = make_float2(1.f, 0.f), ph = make_float2(1.f, 0.f);
        #pragma unroll
        for (int k = 0; k < 7; k++) {
            if ((v >> k) & 1) {
                pl = cmul_s(pl, phw[13 - k]);
                ph = cmul_s(ph, phw[6 - k]);
            }
        }
        PhiRe[t] = ph.x; PhiIm[t] = ph.y;
        int c = v >> 5, r = (v >> 1) & 15, b0 = v & 1;
        ((float*)PloRe)[2 * (r * 4 + c) + b0] = pl.x;
        ((float*)PloIm)[2 * (r * 4 + c) + b0] = pl.y;
    } else if (t < 384) {
        // global scale = (prod cos over layers 1,2)^2 folded into weight LUTs
        float prod = 1.f;
        #pragma unroll
        for (int k = NQ; k < 3 * NQ; k++) prod *= cosw[k];
        prod *= prod;
        if (t < 256) {                        // Wlo(v), v = f bits 0..6
            int v = t - 128; float acc = 0.f;
            #pragma unroll
            for (int k = 0; k < 7; k++)
                acc += hw[13 - k] * (1.f - 2.f * (float)((v >> k) & 1));
            WloF[v] = acc * prod;
        } else {                              // Whi(v), v = f bits 7..13
            int v = t - 256; float acc = 0.f;
            #pragma unroll
            for (int k = 0; k < 7; k++)
                acc += hw[6 - k] * (1.f - 2.f * (float)((v >> k) & 1));
            Whi[v] = acc * prod;
        }
    }

    ull vre[16], vim[16];

    // tangent-form RY on tile bit lb
    auto applyW = [&](float tg, int lb) {
        ull tp = bc(tg), tn = bc(-tg);
        #pragma unroll
        for (int m = 0; m < 8; m++) {
            int l0 = ((m >> lb) << (lb + 1)) | (m & ((1 << lb) - 1));
            int l1 = l0 | (1 << lb);
            ull r0 = f2fma(tn, vre[l1], vre[l0]);
            ull r1 = f2fma(tp, vre[l0], vre[l1]);
            vre[l0] = r0; vre[l1] = r1;
            ull i0 = f2fma(tn, vim[l1], vim[l0]);
            ull i1 = f2fma(tp, vim[l0], vim[l1]);
            vim[l0] = i0; vim[l1] = i1;
        }
    };

    // affine pass bases (padding A(p) = p + (p>>4))
    const int b1 = t + (t >> 4);                               // + 544*r
    const int b2 = (t >> 5) * 544 + (t & 31) + ((t >> 4) & 1); // + 34*r
    const int b3 = 34 * (t >> 1) + (t & 1);                    // + 2r + (r>>3)
    const int b4 = 17 * t;                                     // + r

    // ---- init: closed-form product state through ALL of layer 0 ----
    {
        // base over t bits k=0..8 (amp bit k+1 -> wire 12-k)
        float2 base = (t & 1) ? uw1[12] : uw0[12];
        #pragma unroll
        for (int k = 1; k < 9; k++)
            base = cmul_s(base, ((t >> k) & 1) ? uw1[12 - k] : uw0[12 - k]);
        // r bit m -> wire 3-m : split factors (bits 0,1 -> wires 3,2; bits 2,3 -> wires 1,0)
        float2 g01[4], h[4];
        #pragma unroll
        for (int j = 0; j < 4; j++)
            g01[j] = cmul_s((j & 1) ? uw1[3] : uw0[3], (j & 2) ? uw1[2] : uw0[2]);
        #pragma unroll
        for (int j = 0; j < 4; j++)
            h[j] = cmul_s(base, cmul_s((j & 1) ? uw1[1] : uw0[1], (j & 2) ? uw1[0] : uw0[0]));
        // lane = amp bit 0 = wire 13, packed factors
        ull U13r = pk2(uw0[13].x, uw1[13].x);
        ull U13i = pk2(uw0[13].y, uw1[13].y);
        #pragma unroll
        for (int r = 0; r < 16; r++) {
            float2 mr = cmul_s(h[r >> 2], g01[r & 3]);
            ull mre = bc(mr.x), mim = bc(mr.y), nmim = bc(-mr.y);
            vre[r] = f2fma(mre, U13r, f2mul(nmim, U13i));
            vim[r] = f2fma(mre, U13i, f2mul(mim,  U13r));
        }
        #pragma unroll
        for (int r = 0; r < 16; r++) { sRe[b1 + 544 * r] = vre[r]; sIm[b1 + 544 * r] = vim[r]; }
    }
    __syncthreads();   // state + LUTs ready

    #pragma unroll 1
    for (int L = 1; L < 3; L++) {
        // ---- fold (CNOT chain of layer L-1) + P1 gates of layer L ----
        {
            const int e  = t ^ (t >> 1);
            const int eh = e >> 4;
            #pragma unroll
            for (int r = 0; r < 16; r++) {
                const int C = (r << 1) ^ r;          // compile-time
                int p = e ^ (C << 8);
                int a = p + (eh ^ (C << 4));
                vre[r] = sRe[a]; vim[r] = sIm[a];
            }
            if (t & 1) {   // lane swap (output pair bit0 = t&1)
                #pragma unroll
                for (int r = 0; r < 16; r++) { vre[r] = swp(vre[r]); vim[r] = swp(vim[r]); }
            }
            #pragma unroll
            for (int lb = 0; lb < 4; lb++) applyW(tanw[L * NQ + (3 - lb)], lb);
            __syncthreads();   // all fold reads done before rewrites
            #pragma unroll
            for (int r = 0; r < 16; r++) { sRe[b1 + 544 * r] = vre[r]; sIm[b1 + 544 * r] = vim[r]; }
        }
        __syncthreads();

        // ---- P2: wires 4..7 ----
        {
            #pragma unroll
            for (int r = 0; r < 16; r++) { vre[r] = sRe[b2 + 34 * r]; vim[r] = sIm[b2 + 34 * r]; }
            #pragma unroll
            for (int lb = 0; lb < 4; lb++) applyW(tanw[L * NQ + (7 - lb)], lb);
            #pragma unroll
            for (int r = 0; r < 16; r++) { sRe[b2 + 34 * r] = vre[r]; sIm[b2 + 34 * r] = vim[r]; }
        }
        __syncwarp(0xffffffffu);   // P2->P3 warp-local (pair bits 12..9 = warp id)

        // ---- P3: wires 8..11 ----
        {
            #pragma unroll
            for (int r = 0; r < 16; r++) {
                int o = b3 + 2 * r + (r >> 3);
                vre[r] = sRe[o]; vim[r] = sIm[o];
            }
            #pragma unroll
            for (int lb = 0; lb < 4; lb++) applyW(tanw[L * NQ + (11 - lb)], lb);
            #pragma unroll
            for (int r = 0; r < 16; r++) {
                int o = b3 + 2 * r + (r >> 3);
                sRe[o] = vre[r]; sIm[o] = vim[r];
            }
        }
        __syncwarp(0xffffffffu);   // P3->P4 warp-local

        // ---- P4: wires 12,13; phase at L=1; fused measurement at L=2 ----
        {
            #pragma unroll
            for (int r = 0; r < 16; r++) { vre[r] = sRe[b4 + r]; vim[r] = sIm[b4 + r]; }
            applyW(tanw[L * NQ + 12], 0);
            {
                // wire 13 (lane): v' = v + tm * swp(v)
                ull tm = pk2(-tanw[L * NQ + 13], tanw[L * NQ + 13]);
                #pragma unroll
                for (int r = 0; r < 16; r++) {
                    vre[r] = f2fma(tm, swp(vre[r]), vre[r]);
                    vim[r] = f2fma(tm, swp(vim[r]), vim[r]);
                }
            }
            if (L == 1) {
                float fr = PhiRe[t >> 2];
                float fi = PhiIm[t >> 2];
                ull fr2 = bc(fr), fi2 = bc(fi), nfi2 = bc(-fi), n1 = bc(-1.f);
                const int c = t & 3;
                #pragma unroll
                for (int r = 0; r < 16; r++) {
                    ull pr2 = PloRe[r * 4 + c];
                    ull pi2 = PloIm[r * 4 + c];
                    ull cr  = f2fma(fr2, pr2, f2mul(nfi2, pi2));
                    ull ci  = f2fma(fr2, pi2, f2mul(fi2, pr2));
                    ull nci = f2mul(n1, ci);
                    ull re = vre[r], im = vim[r];
                    vre[r] = f2fma(cr, re, f2mul(nci, im));
                    vim[r] = f2fma(cr, im, f2mul(ci,  re));
                }
                #pragma unroll
                for (int r = 0; r < 16; r++) { sRe[b4 + r] = vre[r]; sIm[b4 + r] = vim[r]; }
                __syncthreads();   // visible to next iteration's fold
            } else {
                // ---- measurement from registers (chain folded, scaled W) ----
                const int ftt = pf_(t << 5);
                const float whi = Whi[ftt >> 7];
                ull acc2 = bc(0.f);
                #pragma unroll
                for (int k = 0; k < 16; k++) {
                    ull pr2 = f2fma(vim[k], vim[k], f2mul(vre[k], vre[k]));
                    int f0 = (ftt ^ pf_(k << 1)) & 127;
                    float w0 = WloF[f0]     + whi;
                    float w1 = WloF[f0 ^ 1] + whi;
                    acc2 = f2fma(pr2, pk2(w0, w1), acc2);
                }
                float2 ac = upk(acc2);
                float acc = ac.x + ac.y;
                #pragma unroll
                for (int o = 16; o > 0; o >>= 1)
                    acc += __shfl_xor_sync(0xffffffffu, acc, o);
                if ((t & 31) == 0) red[t >> 5] = acc;
                __syncthreads();
                if (t == 0) {
                    float s = 0.f;
                    #pragma unroll
                    for (int w = 0; w < TPB / 32; w++) s += red[w];
                    out[b] = s + hb[0];
                }
            }
        }
    }
}

extern "C" void kernel_launch(void* const* d_in, const int* in_sizes, int n_in,
                              void* d_out, int out_size) {
    const float* sb = (const float*)d_in[0];
    const float* vp = (const float*)d_in[1];
    const float* hw = (const float*)d_in[2];
    const float* hb = (const float*)d_in[3];
    float* out = (float*)d_out;

    const int B = in_sizes[0] / NQ;
    const size_t smem = (size_t)(SPAD * 2 + 64 * 2 + 64) * 8   // sRe,sIm,Plo*,Wlo2
                      + (48 + 48) * 4                          // tanw, cosw
                      + (16 + 16 + 16) * 8                     // phw, uw0, uw1
                      + (128 * 2 + 128 + 16) * 4;              // PhiRe/Im, Whi, red
    cudaFuncSetAttribute(qsim_kernel,
                         cudaFuncAttributeMaxDynamicSharedMemorySize, (int)smem);
    qsim_kernel<<<B, TPB, smem>>>(sb, vp, hw, hb, out);
}

// round 14
// speedup vs baseline: 1.5913x; 1.1087x over previous
#include <cuda_runtime.h>
#include <cstdint>

#define NQ   14
#define TPB  512
typedef unsigned long long ull;

__device__ __forceinline__ int pf_(int x) {
    x ^= x >> 1; x ^= x >> 2; x ^= x >> 4; x ^= x >> 8;
    return x;
}

// ---- packed f32x2 on native 64-bit regs ----
__device__ __forceinline__ ull f2mul(ull a, ull b) {
    ull r; asm("mul.rn.f32x2 %0,%1,%2;" : "=l"(r) : "l"(a), "l"(b)); return r;
}
__device__ __forceinline__ ull f2fma(ull a, ull b, ull c) {
    ull r; asm("fma.rn.f32x2 %0,%1,%2,%3;" : "=l"(r) : "l"(a), "l"(b), "l"(c)); return r;
}
__device__ __forceinline__ ull pk2(float x, float y) {
    ull r; asm("mov.b64 %0,{%1,%2};" : "=l"(r) : "f"(x), "f"(y)); return r;
}
__device__ __forceinline__ float2 upk(ull a) {
    float2 r; asm("mov.b64 {%0,%1},%2;" : "=f"(r.x), "=f"(r.y) : "l"(a)); return r;
}
__device__ __forceinline__ ull swp(ull a) { float2 t = upk(a); return pk2(t.y, t.x); }
__device__ __forceinline__ ull bc(float x) { return pk2(x, x); }

__device__ __forceinline__ float2 cmul_s(float2 a, float2 b) {
    return make_float2(a.x * b.x - a.y * b.y, a.x * b.y + a.y * b.x);
}

// ---- fp16 pack/unpack of a pair: lo32 = half2(re0,re1), hi32 = half2(im0,im1) ----
__device__ __forceinline__ ull pkh(ull re, ull im) {
    float2 a = upk(re), b = upk(im);
    unsigned hre, him;
    asm("cvt.rn.f16x2.f32 %0,%1,%2;" : "=r"(hre) : "f"(a.y), "f"(a.x));
    asm("cvt.rn.f16x2.f32 %0,%1,%2;" : "=r"(him) : "f"(b.y), "f"(b.x));
    ull r; asm("mov.b64 %0,{%1,%2};" : "=l"(r) : "r"(hre), "r"(him));
    return r;
}
__device__ __forceinline__ void uph(ull p, ull& re, ull& im) {
    unsigned hre, him;
    asm("mov.b64 {%0,%1},%2;" : "=r"(hre), "=r"(him) : "l"(p));
    float r0, r1, i0, i1;
    asm("{.reg .b16 l,h; mov.b32 {l,h},%2; cvt.f32.f16 %0,l; cvt.f32.f16 %1,h;}"
        : "=f"(r0), "=f"(r1) : "r"(hre));
    asm("{.reg .b16 l,h; mov.b32 {l,h},%2; cvt.f32.f16 %0,l; cvt.f32.f16 %1,h;}"
        : "=f"(i0), "=f"(i1) : "r"(him));
    re = pk2(r0, r1); im = pk2(i0, i1);
}
__device__ __forceinline__ void uphs(ull p, ull& re, ull& im) {  // lane-swapped
    unsigned hre, him;
    asm("mov.b64 {%0,%1},%2;" : "=r"(hre), "=r"(him) : "l"(p));
    float r0, r1, i0, i1;
    asm("{.reg .b16 l,h; mov.b32 {l,h},%2; cvt.f32.f16 %0,l; cvt.f32.f16 %1,h;}"
        : "=f"(r0), "=f"(r1) : "r"(hre));
    asm("{.reg .b16 l,h; mov.b32 {l,h},%2; cvt.f32.f16 %0,l; cvt.f32.f16 %1,h;}"
        : "=f"(i0), "=f"(i1) : "r"(him));
    re = pk2(r1, r0); im = pk2(i1, i0);
}

#define SPAD 8704   // 8192 pairs + 512 pad (1 per 16), pad A(p)=p+(p>>4)

__global__ void __launch_bounds__(TPB, 2)
qsim_kernel(const float* __restrict__ sb, const float* __restrict__ vp,
            const float* __restrict__ hw, const float* __restrict__ hb,
            float* __restrict__ out)
{
    extern __shared__ unsigned char smraw[];
    ull*    sPK   = (ull*)smraw;             // 8704 (8B per pair, fp16 packed)
    ull*    PloRe = sPK + SPAD;              // 64 (layer-1), [r*8+c]
    ull*    PloIm = PloRe + 64;              // 64
    ull*    Wlo2  = PloIm + 64;              // 64 (scalar view Wlo[128])
    float*  tanw  = (float*)(Wlo2 + 64);     // 48 (uses 14..41)
    float*  cosw  = tanw + 48;               // 48 (uses 14..41)
    float2* phw   = (float2*)(cosw + 48);    // 16 (14 used: layer-1 RZ)
    float2* uw0   = phw + 16;                // 16 (layer-0 folded |0>-comp)
    float2* uw1   = uw0 + 16;                // 16
    float*  PhiRe = (float*)(uw1 + 16);      // 128
    float*  PhiIm = PhiRe + 128;             // 128
    float*  Whi   = PhiIm + 128;             // 128
    float*  red   = Whi + 128;               // 16
    float*  WloF  = (float*)Wlo2;

    const int t = threadIdx.x;
    const int b = blockIdx.x;

    // ---- stage 1: parameter staging ----
    if (t < NQ) {
        float xs, xc; sincosf(0.5f * sb[b * NQ + t], &xs, &xc);
        float sa, ca; sincosf(0.5f * vp[t * 3 + 0], &sa, &ca);
        float sp, cp; sincosf(vp[t * 3 + 1], &sp, &cp);
        uw0[t] = make_float2(ca * xc, sa * xs);
        float u1r = sa * xc, u1i = -ca * xs;
        uw1[t] = make_float2(cp * u1r - sp * u1i, sp * u1r + cp * u1i);
    }
    if (t >= 64 && t < 64 + 2 * NQ) {        // lw in [14,42): layers 1,2
        int lw = t - 64 + NQ;
        float sa, ca;
        sincosf(0.5f * vp[lw * 3 + 0], &sa, &ca);
        tanw[lw] = __fdividef(sa, ca);
        cosw[lw] = ca;
        if (lw < 2 * NQ) {
            float sp, cp;
            sincosf(vp[lw * 3 + 1], &sp, &cp);
            phw[lw - NQ] = make_float2(cp, sp);
        }
    }
    __syncthreads();

    // ---- stage 2: LUT builds ----
    if (t < 128) {
        int v = t;
        float2 pl = make_float2(1.f, 0.f), ph = make_float2(1.f, 0.f);
        #pragma unroll
        for (int k = 0; k < 7; k++) {
            if ((v >> k) & 1) {
                pl = cmul_s(pl, phw[13 - k]);
                ph = cmul_s(ph, phw[6 - k]);
            }
        }
        PhiRe[t] = ph.x; PhiIm[t] = ph.y;
        int c = v >> 4, rr = (v >> 1) & 7, b0 = v & 1;
        ((float*)PloRe)[2 * (rr * 8 + c) + b0] = pl.x;
        ((float*)PloIm)[2 * (rr * 8 + c) + b0] = pl.y;
    } else if (t < 384) {
        float prod = 1.f;
        #pragma unroll
        for (int k = NQ; k < 3 * NQ; k++) prod *= cosw[k];
        prod *= prod;
        if (t < 256) {
            int v = t - 128; float acc = 0.f;
            #pragma unroll
            for (int k = 0; k < 7; k++)
                acc += hw[13 - k] * (1.f - 2.f * (float)((v >> k) & 1));
            WloF[v] = acc * prod;
        } else {
            int v = t - 256; float acc = 0.f;
            #pragma unroll
            for (int k = 0; k < 7; k++)
                acc += hw[6 - k] * (1.f - 2.f * (float)((v >> k) & 1));
            Whi[v] = acc * prod;
        }
    }

    ull vre[8], vim[8];

    // tangent-form RY on tile bit lb (8-pair tile)
    auto applyW3 = [&](float tg, int lb) {
        ull tp = bc(tg), tn = bc(-tg);
        #pragma unroll
        for (int m = 0; m < 4; m++) {
            int l0 = ((m >> lb) << (lb + 1)) | (m & ((1 << lb) - 1));
            int l1 = l0 | (1 << lb);
            ull r0 = f2fma(tn, vre[l1], vre[l0]);
            ull r1 = f2fma(tp, vre[l0], vre[l1]);
            vre[l0] = r0; vre[l1] = r1;
            ull i0 = f2fma(tn, vim[l1], vim[l0]);
            ull i1 = f2fma(tp, vim[l0], vim[l1]);
            vim[l0] = i0; vim[l1] = i1;
        }
    };

    // ---- init: layer-0 product state DIRECTLY in post-chain-0 basis,
    //      then layer-1 wires 0..2 in-register, write in P1 layout ----
    // Post-chain amp j: factor selector for amp bit k is j_k ^ j_{k+1}.
    {
        const int et = t ^ (t >> 1);         // selectors for wires 12..5 (bits 0..7)
        float2 base = (et & 1) ? uw1[12] : uw0[12];
        #pragma unroll
        for (int k = 1; k < 8; k++)
            base = cmul_s(base, ((et >> k) & 1) ? uw1[12 - k] : uw0[12 - k]);
        const int t8 = (t >> 8) & 1;
        // wire 13 (lane): selector = lane ^ (t&1)
        ull U13r = (t & 1) ? pk2(uw1[13].x, uw0[13].x) : pk2(uw0[13].x, uw1[13].x);
        ull U13i = (t & 1) ? pk2(uw1[13].y, uw0[13].y) : pk2(uw0[13].y, uw1[13].y);
        #pragma unroll
        for (int h = 0; h < 2; h++) {
            const int tv = t + (h << 9);
            float2 b4f = cmul_s(base, (t8 ^ h) ? uw1[4] : uw0[4]);   // wire 4: t8^h
            float2 bh0 = cmul_s(b4f, h ? uw1[3] : uw0[3]);           // wire 3: h^r0
            float2 bh1 = cmul_s(b4f, h ? uw0[3] : uw1[3]);
            #pragma unroll
            for (int r = 0; r < 8; r++) {
                const int s2 = (r ^ (r >> 1)) & 1;          // wire 2: r0^r1
                const int s1 = ((r >> 1) ^ (r >> 2)) & 1;   // wire 1: r1^r2
                const int s0 = (r >> 2) & 1;                // wire 0: r2
                float2 m = cmul_s((r & 1) ? bh1 : bh0, s2 ? uw1[2] : uw0[2]);
                m = cmul_s(m, s1 ? uw1[1] : uw0[1]);
                m = cmul_s(m, s0 ? uw1[0] : uw0[0]);
                vre[r] = f2fma(bc(m.x), U13r, f2mul(bc(-m.y), U13i));
                vim[r] = f2fma(bc(m.x), U13i, f2mul(bc(m.y),  U13r));
            }
            #pragma unroll
            for (int lb = 0; lb < 3; lb++) applyW3(tanw[NQ + 2 - lb], lb);
            const int b1 = tv + (tv >> 4);
            #pragma unroll
            for (int r = 0; r < 8; r++) sPK[b1 + 1088 * r] = pkh(vre[r], vim[r]);
        }
    }
    __syncthreads();

    #pragma unroll 1
    for (int L = 1; L < 3; L++) {
        const int lt = L * NQ;
        // ---- P2: wires 3..5 ----
        #pragma unroll
        for (int h = 0; h < 2; h++) {
            const int tv = t + (h << 9);
            const int b2 = 1088 * (tv >> 7) + (tv & 127) + ((tv >> 4) & 7);
            #pragma unroll
            for (int r = 0; r < 8; r++) uph(sPK[b2 + 136 * r], vre[r], vim[r]);
            #pragma unroll
            for (int lb = 0; lb < 3; lb++) applyW3(tanw[lt + 5 - lb], lb);
            #pragma unroll
            for (int r = 0; r < 8; r++) sPK[b2 + 136 * r] = pkh(vre[r], vim[r]);
        }
        __syncthreads();

        // ---- P3: wires 6..8 ----
        #pragma unroll
        for (int h = 0; h < 2; h++) {
            const int tv = t + (h << 9);
            const int b3 = 136 * (tv >> 4) + (tv & 15);
            #pragma unroll
            for (int r = 0; r < 8; r++) uph(sPK[b3 + 17 * r], vre[r], vim[r]);
            #pragma unroll
            for (int lb = 0; lb < 3; lb++) applyW3(tanw[lt + 8 - lb], lb);
            #pragma unroll
            for (int r = 0; r < 8; r++) sPK[b3 + 17 * r] = pkh(vre[r], vim[r]);
        }
        __syncthreads();

        // ---- P4: wires 9..11 ----
        #pragma unroll
        for (int h = 0; h < 2; h++) {
            const int tv = t + (h << 9);
            const int b4 = 17 * (tv & 511) + (tv >> 9);
            #pragma unroll
            for (int r = 0; r < 8; r++) uph(sPK[b4 + 2 * r], vre[r], vim[r]);
            #pragma unroll
            for (int lb = 0; lb < 3; lb++) applyW3(tanw[lt + 11 - lb], lb);
            #pragma unroll
            for (int r = 0; r < 8; r++) sPK[b4 + 2 * r] = pkh(vre[r], vim[r]);
        }
        __syncthreads();

        if (L == 1) {
            // ---- P5: wire 12 + wire 13 (lane) + consolidated layer-1 phase ----
            #pragma unroll
            for (int h = 0; h < 2; h++) {
                const int tv = t + (h << 9);
                const int b5 = 8 * tv + (tv >> 1);
                #pragma unroll
                for (int r = 0; r < 8; r++) uph(sPK[b5 + r], vre[r], vim[r]);
                applyW3(tanw[lt + 12], 0);
                ull tm = pk2(-tanw[lt + 13], tanw[lt + 13]);
                #pragma unroll
                for (int r = 0; r < 8; r++) {
                    vre[r] = f2fma(tm, swp(vre[r]), vre[r]);
                    vim[r] = f2fma(tm, swp(vim[r]), vim[r]);
                }
                float fr = PhiRe[tv >> 3], fi = PhiIm[tv >> 3];
                ull fr2 = bc(fr), fi2 = bc(fi), nfi2 = bc(-fi), n1 = bc(-1.f);
                const int c = tv & 7;
                #pragma unroll
                for (int r = 0; r < 8; r++) {
                    ull pr2 = PloRe[r * 8 + c];
                    ull pi2 = PloIm[r * 8 + c];
                    ull cr  = f2fma(fr2, pr2, f2mul(nfi2, pi2));
                    ull ci  = f2fma(fr2, pi2, f2mul(fi2, pr2));
                    ull nci = f2mul(n1, ci);
                    ull re = vre[r], im = vim[r];
                    vre[r] = f2fma(cr, re, f2mul(nci, im));
                    vim[r] = f2fma(cr, im, f2mul(ci,  re));
                }
                #pragma unroll
                for (int r = 0; r < 8; r++) sPK[b5 + r] = pkh(vre[r], vim[r]);
            }
            __syncthreads();

            // ---- fold (chain of layer 1) + P1 gates of layer 2 ----
            {
                ull pkA[8], pkB[8];
                const int e0 = t ^ (t >> 1);
                const int e1 = (t + 512) ^ ((t + 512) >> 1);
                #pragma unroll
                for (int r = 0; r < 8; r++) {
                    const int C = ((r << 1) ^ r) << 9;      // compile-time
                    int q0 = e0 ^ C; pkA[r] = sPK[q0 + (q0 >> 4)];
                    int q1 = e1 ^ C; pkB[r] = sPK[q1 + (q1 >> 4)];
                }
                __syncthreads();   // all fold reads done before any rewrite
                #pragma unroll
                for (int h = 0; h < 2; h++) {
                    const int tv = t + (h << 9);
                    if (t & 1) {
                        #pragma unroll
                        for (int r = 0; r < 8; r++) uphs(h ? pkB[r] : pkA[r], vre[r], vim[r]);
                    } else {
                        #pragma unroll
                        for (int r = 0; r < 8; r++) uph(h ? pkB[r] : pkA[r], vre[r], vim[r]);
                    }
                    #pragma unroll
                    for (int lb = 0; lb < 3; lb++) applyW3(tanw[2 * NQ + 2 - lb], lb);
                    const int b1 = tv + (tv >> 4);
                    #pragma unroll
                    for (int r = 0; r < 8; r++) sPK[b1 + 1088 * r] = pkh(vre[r], vim[r]);
                }
            }
            __syncthreads();
        } else {
            // ---- P5 at L=2: wire 12 + lane 13 + fused measurement ----
            ull acc2 = bc(0.f);
            #pragma unroll
            for (int h = 0; h < 2; h++) {
                const int tv = t + (h << 9);
                const int b5 = 8 * tv + (tv >> 1);
                #pragma unroll
                for (int r = 0; r < 8; r++) uph(sPK[b5 + r], vre[r], vim[r]);
                applyW3(tanw[lt + 12], 0);
                ull tm = pk2(-tanw[lt + 13], tanw[lt + 13]);
                #pragma unroll
                for (int r = 0; r < 8; r++) {
                    vre[r] = f2fma(tm, swp(vre[r]), vre[r]);
                    vim[r] = f2fma(tm, swp(vim[r]), vim[r]);
                }
                const int ftt = pf_(tv << 4);
                const float whi = Whi[ftt >> 7];
                #pragma unroll
                for (int r = 0; r < 8; r++) {
                    ull pr2 = f2fma(vim[r], vim[r], f2mul(vre[r], vre[r]));
                    int f0 = (ftt ^ pf_(r << 1)) & 127;     // pf_(r<<1) compile-time
                    float w0 = WloF[f0]     + whi;
                    float w1 = WloF[f0 ^ 1] + whi;
                    acc2 = f2fma(pr2, pk2(w0, w1), acc2);
                }
            }
            float2 ac = upk(acc2);
            float acc = ac.x + ac.y;
            #pragma unroll
            for (int o = 16; o > 0; o >>= 1)
                acc += __shfl_xor_sync(0xffffffffu, acc, o);
            if ((t & 31) == 0) red[t >> 5] = acc;
            __syncthreads();
            if (t == 0) {
                float s = 0.f;
                #pragma unroll
                for (int w = 0; w < TPB / 32; w++) s += red[w];
                out[b] = s + hb[0];
            }
        }
    }
}

extern "C" void kernel_launch(void* const* d_in, const int* in_sizes, int n_in,
                              void* d_out, int out_size) {
    const float* sb = (const float*)d_in[0];
    const float* vp = (const float*)d_in[1];
    const float* hw = (const float*)d_in[2];
    const float* hb = (const float*)d_in[3];
    float* out = (float*)d_out;

    const int B = in_sizes[0] / NQ;
    const size_t smem = (size_t)(SPAD + 64 * 2 + 64) * 8       // sPK, Plo*, Wlo2
                      + (48 + 48) * 4                          // tanw, cosw
                      + (16 + 16 + 16) * 8                     // phw, uw0, uw1
                      + (128 * 3 + 16) * 4;                    // PhiRe/Im, Whi, red
    cudaFuncSetAttribute(qsim_kernel,
                         cudaFuncAttributeMaxDynamicSharedMemorySize, (int)smem);
    qsim_kernel<<<B, TPB, smem>>>(sb, vp, hw, hb, out);
}

// round 16
// speedup vs baseline: 2.2081x; 1.3876x over previous
#include <cuda_runtime.h>
#include <cuda_fp16.h>
#include <cstdint>

#define NQ   14
#define TPB  512
typedef unsigned long long ull;

__device__ __forceinline__ int pf_(int x) {
    x ^= x >> 1; x ^= x >> 2; x ^= x >> 4; x ^= x >> 8;
    return x;
}

// ---- packed f32x2 (init + measurement only) ----
__device__ __forceinline__ ull f2mul(ull a, ull b) {
    ull r; asm("mul.rn.f32x2 %0,%1,%2;" : "=l"(r) : "l"(a), "l"(b)); return r;
}
__device__ __forceinline__ ull f2fma(ull a, ull b, ull c) {
    ull r; asm("fma.rn.f32x2 %0,%1,%2,%3;" : "=l"(r) : "l"(a), "l"(b), "l"(c)); return r;
}
__device__ __forceinline__ ull pk2(float x, float y) {
    ull r; asm("mov.b64 %0,{%1,%2};" : "=l"(r) : "f"(x), "f"(y)); return r;
}
__device__ __forceinline__ float2 upk(ull a) {
    float2 r; asm("mov.b64 {%0,%1},%2;" : "=f"(r.x), "=f"(r.y) : "l"(a)); return r;
}
__device__ __forceinline__ ull bc(float x) { return pk2(x, x); }

__device__ __forceinline__ float2 cmul_s(float2 a, float2 b) {
    return make_float2(a.x * b.x - a.y * b.y, a.x * b.y + a.y * b.x);
}

// h2 <-> u32 bitcasts (free)
__device__ __forceinline__ __half2 u2h(unsigned u) { __half2 h; *(unsigned*)&h = u; return h; }
__device__ __forceinline__ unsigned h2u(__half2 h) { return *(unsigned*)&h; }

#define SPAD 8704   // 8192 pairs + 512 pad (1 per 16), pad A(p)=p+(p>>4)

__global__ void __launch_bounds__(TPB, 2)
qsim_kernel(const float* __restrict__ sb, const float* __restrict__ vp,
            const float* __restrict__ hw, const float* __restrict__ hb,
            float* __restrict__ out)
{
    extern __shared__ unsigned char smraw[];
    uint2*   sPK  = (uint2*)smraw;            // 8704 x 8B: {re_h2, im_h2} per pair
    __half2* PloR = (__half2*)(sPK + SPAD);   // 64 (layer-1 phase, lane-packed)
    __half2* PloI = PloR + 64;                // 64
    float*   Wlo  = (float*)(PloI + 64);      // 128
    float*   Whi  = Wlo + 128;                // 128
    float*   tanw = Whi + 128;                // 48 (uses 14..41)
    float*   cosw = tanw + 48;                // 48
    float2*  phw  = (float2*)(cosw + 48);     // 16 (layer-1 RZ)
    float2*  uw0  = phw + 16;                 // 16 (layer-0 folded |0>-comp)
    float2*  uw1  = uw0 + 16;                 // 16
    float*   PhiRe= (float*)(uw1 + 16);       // 128
    float*   PhiIm= PhiRe + 128;              // 128
    float*   red  = PhiIm + 128;              // 16

    const int t = threadIdx.x;
    const int b = blockIdx.x;

    // ---- stage 1: parameter staging ----
    if (t < NQ) {
        float xs, xc; sincosf(0.5f * sb[b * NQ + t], &xs, &xc);
        float sa, ca; sincosf(0.5f * vp[t * 3 + 0], &sa, &ca);
        float sp, cp; sincosf(vp[t * 3 + 1], &sp, &cp);
        uw0[t] = make_float2(ca * xc, sa * xs);
        float u1r = sa * xc, u1i = -ca * xs;
        uw1[t] = make_float2(cp * u1r - sp * u1i, sp * u1r + cp * u1i);
    }
    if (t >= 64 && t < 64 + 2 * NQ) {        // lw in [14,42): layers 1,2
        int lw = t - 64 + NQ;
        float sa, ca;
        sincosf(0.5f * vp[lw * 3 + 0], &sa, &ca);
        tanw[lw] = __fdividef(sa, ca);
        cosw[lw] = ca;
        if (lw < 2 * NQ) {
            float sp, cp;
            sincosf(vp[lw * 3 + 1], &sp, &cp);
            phw[lw - NQ] = make_float2(cp, sp);
        }
    }
    __syncthreads();

    // ---- stage 2: LUT builds ----
    if (t < 128) {
        // layer-1 consolidated phase: v = amp low-7 bits, wire 13-k for bit k
        int v = t;
        float2 pl = make_float2(1.f, 0.f), ph = make_float2(1.f, 0.f);
        #pragma unroll
        for (int k = 0; k < 7; k++) {
            if ((v >> k) & 1) {
                pl = cmul_s(pl, phw[13 - k]);
                ph = cmul_s(ph, phw[6 - k]);
            }
        }
        PhiRe[t] = ph.x; PhiIm[t] = ph.y;
        ((__half*)PloR)[v] = __float2half_rn(pl.x);
        ((__half*)PloI)[v] = __float2half_rn(pl.y);
    } else if (t < 384) {
        float prod = 1.f;
        #pragma unroll
        for (int k = NQ; k < 3 * NQ; k++) prod *= cosw[k];
        prod *= prod;
        if (t < 256) {
            int v = t - 128; float acc = 0.f;
            #pragma unroll
            for (int k = 0; k < 7; k++)
                acc += hw[13 - k] * (1.f - 2.f * (float)((v >> k) & 1));
            Wlo[v] = acc * prod;
        } else {
            int v = t - 256; float acc = 0.f;
            #pragma unroll
            for (int k = 0; k < 7; k++)
                acc += hw[6 - k] * (1.f - 2.f * (float)((v >> k) & 1));
            Whi[v] = acc * prod;
        }
    }

    __half2 vre[16], vim[16];

    // tangent-form RY on 16-pair tile, bit lb, in half2
    auto applyW = [&](float tg, int lb) {
        __half2 tp = __float2half2_rn(tg), tn = __float2half2_rn(-tg);
        #pragma unroll
        for (int m = 0; m < 8; m++) {
            int l0 = ((m >> lb) << (lb + 1)) | (m & ((1 << lb) - 1));
            int l1 = l0 | (1 << lb);
            __half2 r0 = __hfma2(tn, vre[l1], vre[l0]);
            __half2 r1 = __hfma2(tp, vre[l0], vre[l1]);
            vre[l0] = r0; vre[l1] = r1;
            __half2 i0 = __hfma2(tn, vim[l1], vim[l0]);
            __half2 i1 = __hfma2(tp, vim[l0], vim[l1]);
            vim[l0] = i0; vim[l1] = i1;
        }
    };

    // affine pass bases (padding A(p) = p + (p>>4)) — R13-verified maps
    const int b1 = t + (t >> 4);                               // + 544*r
    const int b2 = (t >> 5) * 544 + (t & 31) + ((t >> 4) & 1); // + 34*r
    const int b3 = 34 * (t >> 1) + (t & 1);                    // + 2r + (r>>3)
    const int b4 = 17 * t;                                     // + r

    // ---- init: layer-0 product state in post-chain-0 basis + L1 wires 0..3 ----
    // pair p = (r<<9)|t, amp a = (r<<10)|(t<<1)|lane; selector for amp bit k = a_k^a_{k+1}
    {
        const int e = t ^ (t >> 1);          // bits j=0..7 -> wire 12-j
        float2 base = (e & 1) ? uw1[12] : uw0[12];
        #pragma unroll
        for (int k = 1; k < 8; k++)
            base = cmul_s(base, ((e >> k) & 1) ? uw1[12 - k] : uw0[12 - k]);
        const int t8 = (t >> 8) & 1;
        float2 c4[2];                         // wire 4: sel = t8 ^ r0
        c4[0] = cmul_s(base, t8 ? uw1[4] : uw0[4]);
        c4[1] = cmul_s(base, t8 ? uw0[4] : uw1[4]);
        float2 W2[4], V2[4];                  // wires 3,2 / 1,0
        #pragma unroll
        for (int n = 0; n < 4; n++) {
            W2[n] = cmul_s((n & 1) ? uw1[3] : uw0[3], (n & 2) ? uw1[2] : uw0[2]);
            V2[n] = cmul_s((n & 1) ? uw1[1] : uw0[1], (n & 2) ? uw1[0] : uw0[0]);
        }
        // wire 13 (lane): sel = lane ^ t0
        ull U13r = (t & 1) ? pk2(uw1[13].x, uw0[13].x) : pk2(uw0[13].x, uw1[13].x);
        ull U13i = (t & 1) ? pk2(uw1[13].y, uw0[13].y) : pk2(uw0[13].y, uw1[13].y);
        #pragma unroll
        for (int r = 0; r < 16; r++) {
            const int g = r ^ (r >> 1);       // g0->w3, g1->w2, g2->w1, g3->w0
            float2 m = cmul_s(cmul_s(c4[r & 1], W2[g & 3]), V2[(g >> 2) & 3]);
            ull re = f2fma(bc(m.x), U13r, f2mul(bc(-m.y), U13i));
            ull im = f2fma(bc(m.x), U13i, f2mul(bc(m.y),  U13r));
            vre[r] = __float22half2_rn(upk(re));
            vim[r] = __float22half2_rn(upk(im));
        }
        #pragma unroll
        for (int lb = 0; lb < 4; lb++) applyW(tanw[NQ + 3 - lb], lb);
        #pragma unroll
        for (int r = 0; r < 16; r++)
            sPK[b1 + 544 * r] = make_uint2(h2u(vre[r]), h2u(vim[r]));
    }
    __syncthreads();

    #pragma unroll 1
    for (int L = 1; L < 3; L++) {
        const int lt = L * NQ;
        // ---- P2: wires 4..7 ----
        #pragma unroll
        for (int r = 0; r < 16; r++) {
            uint2 w = sPK[b2 + 34 * r];
            vre[r] = u2h(w.x); vim[r] = u2h(w.y);
        }
        #pragma unroll
        for (int lb = 0; lb < 4; lb++) applyW(tanw[lt + 7 - lb], lb);
        #pragma unroll
        for (int r = 0; r < 16; r++)
            sPK[b2 + 34 * r] = make_uint2(h2u(vre[r]), h2u(vim[r]));
        __syncwarp(0xffffffffu);   // P2->P3 warp-local (pair bits 12..9 = warp id)

        // ---- P3: wires 8..11 ----
        #pragma unroll
        for (int r = 0; r < 16; r++) {
            uint2 w = sPK[b3 + 2 * r + (r >> 3)];
            vre[r] = u2h(w.x); vim[r] = u2h(w.y);
        }
        #pragma unroll
        for (int lb = 0; lb < 4; lb++) applyW(tanw[lt + 11 - lb], lb);
        #pragma unroll
        for (int r = 0; r < 16; r++)
            sPK[b3 + 2 * r + (r >> 3)] = make_uint2(h2u(vre[r]), h2u(vim[r]));
        __syncwarp(0xffffffffu);   // P3->P4 warp-local

        // ---- P4: wire 12 (bit 0) + wire 13 (lane); phase at L=1; meas at L=2 ----
        #pragma unroll
        for (int r = 0; r < 16; r++) {
            uint2 w = sPK[b4 + r];
            vre[r] = u2h(w.x); vim[r] = u2h(w.y);
        }
        applyW(tanw[lt + 12], 0);
        {
            float t13 = tanw[lt + 13];
            __half2 tm = __halves2half2(__float2half_rn(-t13), __float2half_rn(t13));
            #pragma unroll
            for (int r = 0; r < 16; r++) {
                vre[r] = __hfma2(tm, __lowhigh2highlow(vre[r]), vre[r]);
                vim[r] = __hfma2(tm, __lowhigh2highlow(vim[r]), vim[r]);
            }
        }
        if (L == 1) {
            // consolidated layer-1 phase: amp a = (t<<5)|(r<<1)|lane
            float fr = PhiRe[t >> 2], fi = PhiIm[t >> 2];
            __half2 fr2 = __float2half2_rn(fr);
            __half2 fi2 = __float2half2_rn(fi);
            __half2 nfi2 = __float2half2_rn(-fi);
            const int i0 = (t & 3) << 4;
            #pragma unroll
            for (int r = 0; r < 16; r++) {
                __half2 plr = PloR[i0 | r], pli = PloI[i0 | r];
                __half2 cr = __hfma2(fr2, plr, __hmul2(nfi2, pli));
                __half2 ci = __hfma2(fr2, pli, __hmul2(fi2,  plr));
                __half2 re = vre[r], im = vim[r];
                vre[r] = __hfma2(cr, re, __hmul2(__hneg2(ci), im));
                vim[r] = __hfma2(cr, im, __hmul2(ci, re));
            }
            #pragma unroll
            for (int r = 0; r < 16; r++)
                sPK[b4 + r] = make_uint2(h2u(vre[r]), h2u(vim[r]));
            __syncthreads();   // P4 writes visible before global fold

            // ---- fold (chain of layer 1) + P1 gates of layer 2 ----
            {
                const int e  = t ^ (t >> 1);
                const int eh = e >> 4;
                #pragma unroll
                for (int r = 0; r < 16; r++) {
                    const int C = (r << 1) ^ r;      // compile-time
                    int p = e ^ (C << 8);
                    int a = p + (eh ^ (C << 4));
                    uint2 w = sPK[a];
                    vre[r] = u2h(w.x); vim[r] = u2h(w.y);
                }
                if (t & 1) {   // lane swap (output pair bit0 = t&1)
                    #pragma unroll
                    for (int r = 0; r < 16; r++) {
                        vre[r] = __lowhigh2highlow(vre[r]);
                        vim[r] = __lowhigh2highlow(vim[r]);
                    }
                }
                #pragma unroll
                for (int lb = 0; lb < 4; lb++) applyW(tanw[2 * NQ + 3 - lb], lb);
                __syncthreads();   // all fold reads done before rewrites
                #pragma unroll
                for (int r = 0; r < 16; r++)
                    sPK[b1 + 544 * r] = make_uint2(h2u(vre[r]), h2u(vim[r]));
            }
            __syncthreads();
        } else {
            // ---- measurement from registers (chain folded, scaled W; fp32) ----
            const int ftt = pf_(t << 5);
            const float whi = Whi[ftt >> 7];
            ull acc2 = bc(0.f);
            #pragma unroll
            for (int r = 0; r < 16; r++) {
                float2 rf = __half22float2(vre[r]);
                float2 mf = __half22float2(vim[r]);
                ull rf2 = pk2(rf.x, rf.y), mf2 = pk2(mf.x, mf.y);
                ull pr2 = f2fma(mf2, mf2, f2mul(rf2, rf2));
                int f0 = (ftt ^ pf_(r << 1)) & 127;   // pf_(r<<1) compile-time
                float w0 = Wlo[f0]     + whi;
                float w1 = Wlo[f0 ^ 1] + whi;
                acc2 = f2fma(pr2, pk2(w0, w1), acc2);
            }
            float2 ac = upk(acc2);
            float acc = ac.x + ac.y;
            #pragma unroll
            for (int o = 16; o > 0; o >>= 1)
                acc += __shfl_xor_sync(0xffffffffu, acc, o);
            if ((t & 31) == 0) red[t >> 5] = acc;
            __syncthreads();
            if (t == 0) {
                float s = 0.f;
                #pragma unroll
                for (int w = 0; w < TPB / 32; w++) s += red[w];
                out[b] = s + hb[0];
            }
        }
    }
}

extern "C" void kernel_launch(void* const* d_in, const int* in_sizes, int n_in,
                              void* d_out, int out_size) {
    const float* sb = (const float*)d_in[0];
    const float* vp = (const float*)d_in[1];
    const float* hw = (const float*)d_in[2];
    const float* hb = (const float*)d_in[3];
    float* out = (float*)d_out;

    const int B = in_sizes[0] / NQ;
    const size_t smem = (size_t)SPAD * 8                       // sPK
                      + 64 * 4 * 2                             // PloR, PloI
                      + (128 + 128) * 4                        // Wlo, Whi
                      + (48 + 48) * 4                          // tanw, cosw
                      + (16 + 16 + 16) * 8                     // phw, uw0, uw1
                      + (128 * 2 + 16) * 4;                    // PhiRe/Im, red
    cudaFuncSetAttribute(qsim_kernel,
                         cudaFuncAttributeMaxDynamicSharedMemorySize, (int)smem);
    qsim_kernel<<<B, TPB, smem>>>(sb, vp, hw, hb, out);
}

// round 17
// speedup vs baseline: 2.2351x; 1.0122x over previous
#include <cuda_runtime.h>
#include <cuda_fp16.h>
#include <cstdint>

#define NQ   14
#define TPB  512
typedef unsigned long long ull;

__device__ __forceinline__ int pf_(int x) {
    x ^= x >> 1; x ^= x >> 2; x ^= x >> 4; x ^= x >> 8;
    return x;
}

// ---- packed f32x2 (init + measurement only) ----
__device__ __forceinline__ ull f2mul(ull a, ull b) {
    ull r; asm("mul.rn.f32x2 %0,%1,%2;" : "=l"(r) : "l"(a), "l"(b)); return r;
}
__device__ __forceinline__ ull f2fma(ull a, ull b, ull c) {
    ull r; asm("fma.rn.f32x2 %0,%1,%2,%3;" : "=l"(r) : "l"(a), "l"(b), "l"(c)); return r;
}
__device__ __forceinline__ ull pk2(float x, float y) {
    ull r; asm("mov.b64 %0,{%1,%2};" : "=l"(r) : "f"(x), "f"(y)); return r;
}
__device__ __forceinline__ float2 upk(ull a) {
    float2 r; asm("mov.b64 {%0,%1},%2;" : "=f"(r.x), "=f"(r.y) : "l"(a)); return r;
}
__device__ __forceinline__ ull bc(float x) { return pk2(x, x); }

__device__ __forceinline__ float2 cmul_s(float2 a, float2 b) {
    return make_float2(a.x * b.x - a.y * b.y, a.x * b.y + a.y * b.x);
}

__device__ __forceinline__ __half2 u2h(unsigned u) { __half2 h; *(unsigned*)&h = u; return h; }
__device__ __forceinline__ unsigned h2u(__half2 h) { return *(unsigned*)&h; }

#define SPAD 8704   // 8192 pairs + 512 pad (1 per 16), pad A(p)=p+(p>>4)

__global__ void __launch_bounds__(TPB, 2)
qsim_kernel(const float* __restrict__ sb, const float* __restrict__ vp,
            const float* __restrict__ hw, const float* __restrict__ hb,
            float* __restrict__ out)
{
    extern __shared__ unsigned char smraw[];
    uint2*   sPK  = (uint2*)smraw;            // 8704 x 8B: {re_h2, im_h2} per pair
    uint2*   PloRI= (uint2*)(sPK + SPAD);     // 64: {re_h2, im_h2} of layer-1 Plo
    float*   Wlo  = (float*)(PloRI + 64);     // 128
    float*   Whi  = Wlo + 128;                // 128
    float*   tanw = Whi + 128;                // 48 (uses 14..41)
    float*   cosw = tanw + 48;                // 48
    float2*  phw  = (float2*)(cosw + 48);     // 16 (layer-1 RZ)
    float2*  uw0  = phw + 16;                 // 16 (layer-0 folded |0>-comp)
    float2*  uw1  = uw0 + 16;                 // 16
    float*   PhiRe= (float*)(uw1 + 16);       // 128
    float*   PhiIm= PhiRe + 128;              // 128
    float*   red  = PhiIm + 128;              // 16

    const int t = threadIdx.x;
    const int b = blockIdx.x;

    // ---- stage 1: parameter staging ----
    if (t < NQ) {
        float xs, xc; sincosf(0.5f * sb[b * NQ + t], &xs, &xc);
        float sa, ca; sincosf(0.5f * vp[t * 3 + 0], &sa, &ca);
        float sp, cp; sincosf(vp[t * 3 + 1], &sp, &cp);
        uw0[t] = make_float2(ca * xc, sa * xs);
        float u1r = sa * xc, u1i = -ca * xs;
        uw1[t] = make_float2(cp * u1r - sp * u1i, sp * u1r + cp * u1i);
    }
    if (t >= 64 && t < 64 + 2 * NQ) {        // lw in [14,42): layers 1,2
        int lw = t - 64 + NQ;
        float sa, ca;
        sincosf(0.5f * vp[lw * 3 + 0], &sa, &ca);
        tanw[lw] = __fdividef(sa, ca);
        cosw[lw] = ca;
        if (lw < 2 * NQ) {
            float sp, cp;
            sincosf(vp[lw * 3 + 1], &sp, &cp);
            phw[lw - NQ] = make_float2(cp, sp);
        }
    }
    __syncthreads();

    // ---- stage 2: LUT builds ----
    if (t < 128) {
        // layer-1 consolidated phase: v = amp low-7 bits, wire 13-k for bit k
        int v = t;
        float2 pl = make_float2(1.f, 0.f), ph = make_float2(1.f, 0.f);
        #pragma unroll
        for (int k = 0; k < 7; k++) {
            if ((v >> k) & 1) {
                pl = cmul_s(pl, phw[13 - k]);
                ph = cmul_s(ph, phw[6 - k]);
            }
        }
        PhiRe[t] = ph.x; PhiIm[t] = ph.y;
        __half* pbase = (__half*)PloRI;       // uint2[j]: halves re(2j,2j+1), im(2j,2j+1)
        pbase[4 * (v >> 1) + (v & 1)]     = __float2half_rn(pl.x);
        pbase[4 * (v >> 1) + (v & 1) + 2] = __float2half_rn(pl.y);
    } else if (t < 384) {
        float prod = 1.f;
        #pragma unroll
        for (int k = NQ; k < 3 * NQ; k++) prod *= cosw[k];
        prod *= prod;
        if (t < 256) {
            int v = t - 128; float acc = 0.f;
            #pragma unroll
            for (int k = 0; k < 7; k++)
                acc += hw[13 - k] * (1.f - 2.f * (float)((v >> k) & 1));
            Wlo[v] = acc * prod;
        } else {
            int v = t - 256; float acc = 0.f;
            #pragma unroll
            for (int k = 0; k < 7; k++)
                acc += hw[6 - k] * (1.f - 2.f * (float)((v >> k) & 1));
            Whi[v] = acc * prod;
        }
    }

    __half2 vre[16], vim[16];

    // tangent-form RY on 16-pair tile, bit lb, in half2
    auto applyW = [&](float tg, int lb) {
        __half2 tp = __float2half2_rn(tg), tn = __float2half2_rn(-tg);
        #pragma unroll
        for (int m = 0; m < 8; m++) {
            int l0 = ((m >> lb) << (lb + 1)) | (m & ((1 << lb) - 1));
            int l1 = l0 | (1 << lb);
            __half2 r0 = __hfma2(tn, vre[l1], vre[l0]);
            __half2 r1 = __hfma2(tp, vre[l0], vre[l1]);
            vre[l0] = r0; vre[l1] = r1;
            __half2 i0 = __hfma2(tn, vim[l1], vim[l0]);
            __half2 i1 = __hfma2(tp, vim[l0], vim[l1]);
            vim[l0] = i0; vim[l1] = i1;
        }
    };

    // wire 12 (pair bit 0 = t&1) via shfl_xor(1): sign +tg for t&1==1, -tg else
    auto applyW12 = [&](float tg) {
        float tgs = (t & 1) ? tg : -tg;
        __half2 ts = __float2half2_rn(tgs);
        #pragma unroll
        for (int r = 0; r < 16; r++) {
            __half2 pr = u2h(__shfl_xor_sync(0xffffffffu, h2u(vre[r]), 1));
            __half2 pi = u2h(__shfl_xor_sync(0xffffffffu, h2u(vim[r]), 1));
            vre[r] = __hfma2(ts, pr, vre[r]);
            vim[r] = __hfma2(ts, pi, vim[r]);
        }
    };

    // affine pass bases (padding A(p) = p + (p>>4)) — verified maps
    const int b1 = t + (t >> 4);                               // + 544*r
    const int b2 = (t >> 5) * 544 + (t & 31) + ((t >> 4) & 1); // + 34*r
    const int b3 = 34 * (t >> 1) + (t & 1);                    // + 2r + (r>>3)

    // ---- init: layer-0 product state in post-chain-0 basis + L1 wires 0..3 ----
    {
        const int e = t ^ (t >> 1);          // selectors for wires 12..5
        float2 base = (e & 1) ? uw1[12] : uw0[12];
        #pragma unroll
        for (int k = 1; k < 8; k++)
            base = cmul_s(base, ((e >> k) & 1) ? uw1[12 - k] : uw0[12 - k]);
        const int t8 = (t >> 8) & 1;
        float2 c4[2];                         // wire 4: sel = t8 ^ r0
        c4[0] = cmul_s(base, t8 ? uw1[4] : uw0[4]);
        c4[1] = cmul_s(base, t8 ? uw0[4] : uw1[4]);
        float2 W2[4], V2[4];                  // wires 3,2 / 1,0
        #pragma unroll
        for (int n = 0; n < 4; n++) {
            W2[n] = cmul_s((n & 1) ? uw1[3] : uw0[3], (n & 2) ? uw1[2] : uw0[2]);
            V2[n] = cmul_s((n & 1) ? uw1[1] : uw0[1], (n & 2) ? uw1[0] : uw0[0]);
        }
        ull U13r = (t & 1) ? pk2(uw1[13].x, uw0[13].x) : pk2(uw0[13].x, uw1[13].x);
        ull U13i = (t & 1) ? pk2(uw1[13].y, uw0[13].y) : pk2(uw0[13].y, uw1[13].y);
        #pragma unroll
        for (int r = 0; r < 16; r++) {
            const int g = r ^ (r >> 1);
            float2 m = cmul_s(cmul_s(c4[r & 1], W2[g & 3]), V2[(g >> 2) & 3]);
            ull re = f2fma(bc(m.x), U13r, f2mul(bc(-m.y), U13i));
            ull im = f2fma(bc(m.x), U13i, f2mul(bc(m.y),  U13r));
            vre[r] = __float22half2_rn(upk(re));
            vim[r] = __float22half2_rn(upk(im));
        }
        #pragma unroll
        for (int lb = 0; lb < 4; lb++) applyW(tanw[NQ + 3 - lb], lb);
        #pragma unroll
        for (int r = 0; r < 16; r++)
            sPK[b1 + 544 * r] = make_uint2(h2u(vre[r]), h2u(vim[r]));
    }
    __syncthreads();

    #pragma unroll 1
    for (int L = 1; L < 3; L++) {
        const int lt = L * NQ;
        // ---- P2: wires 4..7 ----
        #pragma unroll
        for (int r = 0; r < 16; r++) {
            uint2 w = sPK[b2 + 34 * r];
            vre[r] = u2h(w.x); vim[r] = u2h(w.y);
        }
        #pragma unroll
        for (int lb = 0; lb < 4; lb++) applyW(tanw[lt + 7 - lb], lb);
        #pragma unroll
        for (int r = 0; r < 16; r++)
            sPK[b2 + 34 * r] = make_uint2(h2u(vre[r]), h2u(vim[r]));
        __syncwarp(0xffffffffu);   // P2->P3 warp-local (pair bits 12..9 = warp id)

        // ---- P3': wires 8..11 (reg bits) + 12 (shfl) + 13 (lane) ----
        #pragma unroll
        for (int r = 0; r < 16; r++) {
            uint2 w = sPK[b3 + 2 * r + (r >> 3)];
            vre[r] = u2h(w.x); vim[r] = u2h(w.y);
        }
        #pragma unroll
        for (int lb = 0; lb < 4; lb++) applyW(tanw[lt + 11 - lb], lb);
        applyW12(tanw[lt + 12]);
        {
            float t13 = tanw[lt + 13];
            __half2 tm = __halves2half2(__float2half_rn(-t13), __float2half_rn(t13));
            #pragma unroll
            for (int r = 0; r < 16; r++) {
                vre[r] = __hfma2(tm, __lowhigh2highlow(vre[r]), vre[r]);
                vim[r] = __hfma2(tm, __lowhigh2highlow(vim[r]), vim[r]);
            }
        }

        if (L == 1) {
            // consolidated layer-1 phase; amp a = ((t>>1)<<6)|(r<<2)|((t&1)<<1)|lane
            float fr = PhiRe[t >> 2], fi = PhiIm[t >> 2];
            __half2 fr2 = __float2half2_rn(fr);
            __half2 fi2 = __float2half2_rn(fi);
            __half2 nfi2 = __float2half2_rn(-fi);
            const int j0 = ((t & 2) << 4) | (t & 1);
            #pragma unroll
            for (int r = 0; r < 16; r++) {
                uint2 pp = PloRI[j0 + (r << 1)];
                __half2 plr = u2h(pp.x), pli = u2h(pp.y);
                __half2 cr = __hfma2(fr2, plr, __hmul2(nfi2, pli));
                __half2 ci = __hfma2(fr2, pli, __hmul2(fi2,  plr));
                __half2 re = vre[r], im = vim[r];
                vre[r] = __hfma2(cr, re, __hmul2(__hneg2(ci), im));
                vim[r] = __hfma2(cr, im, __hmul2(ci, re));
            }
            #pragma unroll
            for (int r = 0; r < 16; r++)
                sPK[b3 + 2 * r + (r >> 3)] = make_uint2(h2u(vre[r]), h2u(vim[r]));
            __syncthreads();   // P3' writes visible block-wide before global fold

            // ---- fold (chain of layer 1) + P1 gates of layer 2 ----
            {
                const int e  = t ^ (t >> 1);
                const int eh = e >> 4;
                #pragma unroll
                for (int r = 0; r < 16; r++) {
                    const int C = (r << 1) ^ r;      // compile-time
                    int p = e ^ (C << 8);
                    int a = p + (eh ^ (C << 4));
                    uint2 w = sPK[a];
                    vre[r] = u2h(w.x); vim[r] = u2h(w.y);
                }
                if (t & 1) {   // lane swap (output pair bit0 = t&1)
                    #pragma unroll
                    for (int r = 0; r < 16; r++) {
                        vre[r] = __lowhigh2highlow(vre[r]);
                        vim[r] = __lowhigh2highlow(vim[r]);
                    }
                }
                #pragma unroll
                for (int lb = 0; lb < 4; lb++) applyW(tanw[2 * NQ + 3 - lb], lb);
                __syncthreads();   // all fold reads done before rewrites
                #pragma unroll
                for (int r = 0; r < 16; r++)
                    sPK[b1 + 544 * r] = make_uint2(h2u(vre[r]), h2u(vim[r]));
            }
            __syncthreads();
        } else {
            // ---- measurement straight from P3' registers (chain folded) ----
            // f(a) = pf(a); a = ((t>>1)<<6)|(r<<2)|((t&1)<<1)|lane; pf linear in XOR
            const int fbase = pf_(((t >> 1) << 6) | ((t & 1) << 1));
            const float whi = Whi[fbase >> 7];
            ull acc2 = bc(0.f);
            #pragma unroll
            for (int r = 0; r < 16; r++) {
                float2 rf = __half22float2(vre[r]);
                float2 mf = __half22float2(vim[r]);
                ull rf2 = pk2(rf.x, rf.y), mf2 = pk2(mf.x, mf.y);
                ull pr2 = f2fma(mf2, mf2, f2mul(rf2, rf2));
                int f0 = (fbase ^ pf_(r << 2)) & 127;   // pf_(r<<2) compile-time
                float w0 = Wlo[f0]     + whi;
                float w1 = Wlo[f0 ^ 1] + whi;
                acc2 = f2fma(pr2, pk2(w0, w1), acc2);
            }
            float2 ac = upk(acc2);
            float acc = ac.x + ac.y;
            #pragma unroll
            for (int o = 16; o > 0; o >>= 1)
                acc += __shfl_xor_sync(0xffffffffu, acc, o);
            if ((t & 31) == 0) red[t >> 5] = acc;
            __syncthreads();
            if (t == 0) {
                float s = 0.f;
                #pragma unroll
                for (int w = 0; w < TPB / 32; w++) s += red[w];
                out[b] = s + hb[0];
            }
        }
    }
}

extern "C" void kernel_launch(void* const* d_in, const int* in_sizes, int n_in,
                              void* d_out, int out_size) {
    const float* sb = (const float*)d_in[0];
    const float* vp = (const float*)d_in[1];
    const float* hw = (const float*)d_in[2];
    const float* hb = (const float*)d_in[3];
    float* out = (float*)d_out;

    const int B = in_sizes[0] / NQ;
    const size_t smem = (size_t)SPAD * 8                       // sPK
                      + 64 * 8                                 // PloRI
                      + (128 + 128) * 4                        // Wlo, Whi
                      + (48 + 48) * 4                          // tanw, cosw
                      + (16 + 16 + 16) * 8                     // phw, uw0, uw1
                      + (128 * 2 + 16) * 4;                    // PhiRe/Im, red
    cudaFuncSetAttribute(qsim_kernel,
                         cudaFuncAttributeMaxDynamicSharedMemorySize, (int)smem);
    qsim_kernel<<<B, TPB, smem>>>(sb, vp, hw, hb, out);
}